// round 8
// baseline (speedup 1.0000x reference)
#include <cuda_runtime.h>
#include <cuda_fp16.h>
#include <cstdint>
#include <cstddef>

// ---------------- problem sizes ----------------
#define MDIM 8192
#define NDIM 4096
#define KDIM 4096
#define MT 128          // CTA tile M
#define NT 64           // CTA tile N
#define KC 64           // K elements per chunk (fp16 -> 128B rows)
#define NCHUNK (KDIM / KC)          // 64
#define STAGES 3
#define A_TILE 16384                // 128 rows x 128B
#define B_TILE 8192                 // 64 rows x 128B
#define STAGE_BYTES (A_TILE + B_TILE)       // 24576
#define SMEM_BYTES (STAGES * STAGE_BYTES)   // 73728 -> 3 CTAs/SM (216KB)

// ---------------- device scratch (no allocation allowed) ----------------
__device__ __align__(128) __half g_X[(size_t)MDIM * KDIM];
__device__ __align__(128) __half g_W[(size_t)NDIM * KDIM];

// ---------------- PTX helpers (base sm_103 target only) -------------------
static __device__ __forceinline__ uint32_t smem_u32(const void* p) {
    uint32_t a;
    asm("{ .reg .u64 t; cvta.to.shared.u64 t, %1; cvt.u32.u64 %0, t; }" : "=r"(a) : "l"(p));
    return a;
}

#define CP16(dst, src) \
    asm volatile("cp.async.cg.shared.global [%0], [%1], 16;" :: "r"((uint32_t)(dst)), "l"(src) : "memory")
#define CP_COMMIT() asm volatile("cp.async.commit_group;" ::: "memory")
#define CP_WAIT(n)  asm volatile("cp.async.wait_group %0;" :: "n"(n) : "memory")

#define LDSM4(r0, r1, r2, r3, addr) \
    asm volatile("ldmatrix.sync.aligned.m8n8.x4.shared.b16 {%0,%1,%2,%3}, [%4];" \
                 : "=r"(r0), "=r"(r1), "=r"(r2), "=r"(r3) : "r"(addr))

// f16 MMA, fp32 accumulate: D[16x8] += A[16x16] * B[16x8]
#define MMA_F16(d, a0, a1, a2, a3, b0, b1) \
    asm volatile("mma.sync.aligned.m16n8k16.row.col.f32.f16.f16.f32 " \
                 "{%0,%1,%2,%3}, {%4,%5,%6,%7}, {%8,%9}, {%0,%1,%2,%3};" \
                 : "+f"((d)[0]), "+f"((d)[1]), "+f"((d)[2]), "+f"((d)[3]) \
                 : "r"(a0), "r"(a1), "r"(a2), "r"(a3), "r"(b0), "r"(b1))

// ---------------- fused prepass: x fp32->fp16, w int32->fp16 --------------
#define NX4 ((size_t)MDIM * KDIM / 4)
#define NW4 ((size_t)NDIM * KDIM / 4)
__global__ void __launch_bounds__(256) cvt_kernel(const float* __restrict__ x,
                                                  const int* __restrict__ w) {
    const float4* __restrict__ x4 = (const float4*)x;
    const int4* __restrict__ w4 = (const int4*)w;
    uint2* __restrict__ dx = (uint2*)g_X;
    uint2* __restrict__ dw = (uint2*)g_W;
    const size_t total = NX4 + NW4;
    size_t stride = (size_t)gridDim.x * blockDim.x;
    for (size_t i = (size_t)blockIdx.x * blockDim.x + threadIdx.x; i < total; i += stride) {
        if (i < NX4) {
            float4 v = x4[i];
            uint32_t h0 = __half_as_ushort(__float2half_rn(v.x));
            uint32_t h1 = __half_as_ushort(__float2half_rn(v.y));
            uint32_t h2 = __half_as_ushort(__float2half_rn(v.z));
            uint32_t h3 = __half_as_ushort(__float2half_rn(v.w));
            uint2 p;
            p.x = h0 | (h1 << 16);
            p.y = h2 | (h3 << 16);
            dx[i] = p;
        } else {
            const size_t j = i - NX4;
            int4 v = w4[j];
            uint32_t h0 = __half_as_ushort(__int2half_rn(v.x));
            uint32_t h1 = __half_as_ushort(__int2half_rn(v.y));
            uint32_t h2 = __half_as_ushort(__int2half_rn(v.z));
            uint32_t h3 = __half_as_ushort(__int2half_rn(v.w));
            uint2 p;
            p.x = h0 | (h1 << 16);
            p.y = h2 | (h3 << 16);
            dw[j] = p;
        }
    }
}

// ---------------- main GEMM: mma.sync f16 (f32 acc), cp.async 3-stage -----
// 256 threads = 8 warps. CTA tile 128(M) x 64(N); warp tile 32(M) x 32(N).
// 72KB smem + <=84 regs -> 3 CTAs/SM: three independent MMA streams per SM
// hide each other's barrier-collapse and LDSM bubbles.
__global__ void __launch_bounds__(256, 3) qgemm_kernel(
    const float* __restrict__ scale,
    const float* __restrict__ bias,
    float* __restrict__ out
) {
    extern __shared__ char smem[];
    const uint32_t sbase = smem_u32(smem);
    const int tid = threadIdx.x;
    const int m0 = blockIdx.y * MT;
    const int n0 = blockIdx.x * NT;

    const int lane = tid & 31;
    const int wid = tid >> 5;
    const int wm = wid & 3;      // 4 M-groups of 32 rows
    const int wn = wid >> 2;     // 2 N-groups of 32 cols

    // gmem byte-bases (row stride = KDIM * 2 bytes = 8192 = 1<<13)
    const char* pX = (const char*)g_X + ((size_t)m0 << 13);
    const char* pW = (const char*)g_W + ((size_t)n0 << 13);

    // ldmatrix address components (proven pattern)
    const int rA = 32 * wm + (lane & 7) + ((lane >> 3) & 1) * 8;
    const int kaddA = ((lane >> 4) & 1) * 16;
    const uint32_t xmA = (uint32_t)((lane & 7) << 4);
    const int nrb = 32 * wn + (lane & 7) + ((lane >> 4) & 1) * 8;
    const int kaddB = ((lane >> 3) & 1) * 16;
    const uint32_t xmB = (uint32_t)((lane & 7) << 4);

    float acc[2][4][4];
    #pragma unroll
    for (int a = 0; a < 2; ++a)
        #pragma unroll
        for (int b = 0; b < 4; ++b)
            #pragma unroll
            for (int c = 0; c < 4; ++c) acc[a][b][c] = 0.0f;

    // ---- stage loader: A 16KB (4 granules/thread) + B 8KB (2/thread) ----
    auto load_stage = [&](int stg, int c) {
        const uint32_t st = sbase + (uint32_t)stg * STAGE_BYTES;
        const uint32_t ko = (uint32_t)c << 7;       // c * 128 bytes along K
        #pragma unroll
        for (int i = 0; i < 4; ++i) {               // A: rows 0..127
            const int g = tid + i * 256;
            const int row = g >> 3;
            const int col = (g & 7) << 4;
            const uint32_t soff = (uint32_t)(row * 128) + ((uint32_t)col ^ (uint32_t)((row & 7) << 4));
            CP16(st + soff, pX + (((size_t)row << 13) + ko + col));
        }
        #pragma unroll
        for (int i = 0; i < 2; ++i) {               // B: rows 0..63
            const int g = tid + i * 256;
            const int row = g >> 3;
            const int col = (g & 7) << 4;
            const uint32_t soff = (uint32_t)(row * 128) + ((uint32_t)col ^ (uint32_t)((row & 7) << 4));
            CP16(st + A_TILE + soff, pW + (((size_t)row << 13) + ko + col));
        }
    };

    // ---- prologue: stages 0,1 ----
    load_stage(0, 0); CP_COMMIT();
    load_stage(1, 1); CP_COMMIT();

    // ---- mainloop ----
    int s_cur = 0;          // stage being computed
    int s_nxt = 2;          // stage to fill with chunk c+2
    for (int c = 0; c < NCHUNK; ++c) {
        CP_WAIT(1);
        __syncthreads();

        const uint32_t st = sbase + (uint32_t)s_cur * STAGE_BYTES;
        const uint32_t aA = st + (uint32_t)(rA * 128);
        const uint32_t aB = st + A_TILE + (uint32_t)(nrb * 128);

        // pull the first k-step's fragments ahead of the cp.async burst so
        // the first MMAs don't queue behind LSU store-issues
        uint32_t af0[4], af1[4], bf0[4], bf1[4];
        {
            const uint32_t kA = ((uint32_t)kaddA) ^ xmA;
            const uint32_t kB = ((uint32_t)kaddB) ^ xmB;
            LDSM4(af0[0], af0[1], af0[2], af0[3], aA + kA);
            LDSM4(af1[0], af1[1], af1[2], af1[3], aA + (uint32_t)(16 * 128) + kA);
            LDSM4(bf0[0], bf0[1], bf0[2], bf0[3], aB + kB);
            LDSM4(bf1[0], bf1[1], bf1[2], bf1[3], aB + (uint32_t)(16 * 128) + kB);
        }

        if (c + 2 < NCHUNK) load_stage(s_nxt, c + 2);
        CP_COMMIT();

        #pragma unroll
        for (int ks = 0; ks < 4; ++ks) {
            if (ks > 0) {
                const uint32_t kA = ((uint32_t)(ks * 32 + kaddA)) ^ xmA;
                const uint32_t kB = ((uint32_t)(ks * 32 + kaddB)) ^ xmB;
                LDSM4(af0[0], af0[1], af0[2], af0[3], aA + kA);
                LDSM4(af1[0], af1[1], af1[2], af1[3], aA + (uint32_t)(16 * 128) + kA);
                LDSM4(bf0[0], bf0[1], bf0[2], bf0[3], aB + kB);
                LDSM4(bf1[0], bf1[1], bf1[2], bf1[3], aB + (uint32_t)(16 * 128) + kB);
            }
            #pragma unroll
            for (int nt = 0; nt < 4; ++nt) {
                const uint32_t b0 = (nt < 2) ? bf0[nt * 2] : bf1[(nt - 2) * 2];
                const uint32_t b1 = (nt < 2) ? bf0[nt * 2 + 1] : bf1[(nt - 2) * 2 + 1];
                MMA_F16(acc[0][nt], af0[0], af0[1], af0[2], af0[3], b0, b1);
                MMA_F16(acc[1][nt], af1[0], af1[1], af1[2], af1[3], b0, b1);
            }
        }
        // rotate stages
        s_cur = (s_cur == 2) ? 0 : s_cur + 1;
        s_nxt = (s_nxt == 2) ? 0 : s_nxt + 1;
    }

    // ---- epilogue: y = scale[n] * acc + bias[n] ----
    const int ncol = n0 + 32 * wn + 2 * (lane & 3);
    const float* scn = scale + ncol;
    const float* bin = bias + ncol;
    #pragma unroll
    for (int mt = 0; mt < 2; ++mt) {
        const int mr0 = m0 + 32 * wm + 16 * mt + (lane >> 2);
        const int mr1 = mr0 + 8;
        float* o0 = out + (size_t)mr0 * NDIM + ncol;
        float* o1 = out + (size_t)mr1 * NDIM + ncol;
        #pragma unroll
        for (int nt = 0; nt < 4; ++nt) {
            const float2 ws = *(const float2*)(scn + 8 * nt);
            const float2 bb = *(const float2*)(bin + 8 * nt);
            float2 v0, v1;
            v0.x = ws.x * acc[mt][nt][0] + bb.x;
            v0.y = ws.y * acc[mt][nt][1] + bb.y;
            v1.x = ws.x * acc[mt][nt][2] + bb.x;
            v1.y = ws.y * acc[mt][nt][3] + bb.y;
            *(float2*)(o0 + 8 * nt) = v0;
            *(float2*)(o1 + 8 * nt) = v1;
        }
    }
}

// ---------------- launcher ----------------
extern "C" void kernel_launch(void* const* d_in, const int* in_sizes, int n_in,
                              void* d_out, int out_size) {
    const float* x     = (const float*)d_in[0];
    const int*   w     = (const int*)d_in[1];
    const float* scale = (const float*)d_in[2];
    const float* bias  = (const float*)d_in[3];
    float* out = (float*)d_out;

    cudaFuncSetAttribute(qgemm_kernel, cudaFuncAttributeMaxDynamicSharedMemorySize, SMEM_BYTES);

    cvt_kernel<<<4096, 256>>>(x, w);

    dim3 grid(NDIM / NT, MDIM / MT);   // (64, 64) = 4096 CTAs
    qgemm_kernel<<<grid, 256, SMEM_BYTES>>>(scale, bias, out);
}

// round 9
// speedup vs baseline: 1.0939x; 1.0939x over previous
#include <cuda_runtime.h>
#include <cuda_fp16.h>
#include <cstdint>
#include <cstddef>

// ---------------- problem sizes ----------------
#define MDIM 8192
#define NDIM 4096
#define KDIM 4096
#define MT 128          // CTA tile M
#define NT 128          // CTA tile N
#define KC 64           // K elements per chunk (fp16 -> 128B rows)
#define NCHUNK (KDIM / KC)          // 64
#define STAGES 3
#define A_TILE 16384                // 128 rows x 128B
#define B_TILE 16384                // 128 rows x 128B
#define STAGE_BYTES (A_TILE + B_TILE)       // 32768
#define SMEM_BYTES (1024 + STAGES * STAGE_BYTES)   // 99328 -> 2 CTAs/SM

// ---------------- device scratch (no allocation allowed) ----------------
__device__ __align__(128) __half g_X[(size_t)MDIM * KDIM];
__device__ __align__(128) __half g_W[(size_t)NDIM * KDIM];

// ---------------- PTX helpers (base sm_103 target only) -------------------
static __device__ __forceinline__ uint32_t smem_u32(const void* p) {
    uint32_t a;
    asm("{ .reg .u64 t; cvta.to.shared.u64 t, %1; cvt.u32.u64 %0, t; }" : "=r"(a) : "l"(p));
    return a;
}

#define CP16(dst, src) \
    asm volatile("cp.async.cg.shared.global [%0], [%1], 16;" :: "r"((uint32_t)(dst)), "l"(src) : "memory")

// arrive on mbarrier when this thread's prior cp.asyncs have completed
#define CP_ARRIVE(mbar) \
    asm volatile("cp.async.mbarrier.arrive.noinc.shared.b64 [%0];" :: "r"((uint32_t)(mbar)) : "memory")

#define MBARRIER_INIT(addr, count) \
    asm volatile("mbarrier.init.shared.b64 [%0], %1;" :: "r"((uint32_t)(addr)), "r"((uint32_t)(count)) : "memory")

#define MBARRIER_ARRIVE(addr) \
    asm volatile("mbarrier.arrive.shared.b64 _, [%0];" :: "r"((uint32_t)(addr)) : "memory")

#define MBARRIER_WAIT_PARITY(mbar_smem_addr, phase_parity) do { \
    uint32_t _mbar = (uint32_t)(mbar_smem_addr); \
    uint32_t _parity = (uint32_t)(phase_parity); \
    uint32_t _done; \
    asm volatile( \
        "{\n\t" \
        ".reg .pred p;\n\t" \
        "mbarrier.try_wait.parity.acquire.cta.shared::cta.b64 p, [%1], %2;\n\t" \
        "selp.b32 %0, 1, 0, p;\n\t" \
        "}" \
        : "=r"(_done) : "r"(_mbar), "r"(_parity) : "memory"); \
    if (!_done) { \
        asm volatile( \
            "{\n\t" \
            ".reg .pred P1;\n\t" \
            "WAIT_LOOP_%=:\n\t" \
            "mbarrier.try_wait.parity.acquire.cta.shared::cta.b64 P1, [%0], %1, 0x989680;\n\t" \
            "@P1 bra.uni WAIT_DONE_%=;\n\t" \
            "bra.uni WAIT_LOOP_%=;\n\t" \
            "WAIT_DONE_%=:\n\t" \
            "}" \
            :: "r"(_mbar), "r"(_parity) : "memory"); \
    } \
} while (0)

#define LDSM4(r0, r1, r2, r3, addr) \
    asm volatile("ldmatrix.sync.aligned.m8n8.x4.shared.b16 {%0,%1,%2,%3}, [%4];" \
                 : "=r"(r0), "=r"(r1), "=r"(r2), "=r"(r3) : "r"(addr))

// f16 MMA, fp32 accumulate: D[16x8] += A[16x16] * B[16x8]
#define MMA_F16(d, a0, a1, a2, a3, b0, b1) \
    asm volatile("mma.sync.aligned.m16n8k16.row.col.f32.f16.f16.f32 " \
                 "{%0,%1,%2,%3}, {%4,%5,%6,%7}, {%8,%9}, {%0,%1,%2,%3};" \
                 : "+f"((d)[0]), "+f"((d)[1]), "+f"((d)[2]), "+f"((d)[3]) \
                 : "r"(a0), "r"(a1), "r"(a2), "r"(a3), "r"(b0), "r"(b1))

// ---------------- fused prepass: x fp32->fp16, w int32->fp16 --------------
#define NX4 ((size_t)MDIM * KDIM / 4)
#define NW4 ((size_t)NDIM * KDIM / 4)
__global__ void __launch_bounds__(256) cvt_kernel(const float* __restrict__ x,
                                                  const int* __restrict__ w) {
    const float4* __restrict__ x4 = (const float4*)x;
    const int4* __restrict__ w4 = (const int4*)w;
    uint2* __restrict__ dx = (uint2*)g_X;
    uint2* __restrict__ dw = (uint2*)g_W;
    const size_t total = NX4 + NW4;
    size_t stride = (size_t)gridDim.x * blockDim.x;
    for (size_t i = (size_t)blockIdx.x * blockDim.x + threadIdx.x; i < total; i += stride) {
        if (i < NX4) {
            float4 v = x4[i];
            uint32_t h0 = __half_as_ushort(__float2half_rn(v.x));
            uint32_t h1 = __half_as_ushort(__float2half_rn(v.y));
            uint32_t h2 = __half_as_ushort(__float2half_rn(v.z));
            uint32_t h3 = __half_as_ushort(__float2half_rn(v.w));
            uint2 p;
            p.x = h0 | (h1 << 16);
            p.y = h2 | (h3 << 16);
            dx[i] = p;
        } else {
            const size_t j = i - NX4;
            int4 v = w4[j];
            uint32_t h0 = __half_as_ushort(__int2half_rn(v.x));
            uint32_t h1 = __half_as_ushort(__int2half_rn(v.y));
            uint32_t h2 = __half_as_ushort(__int2half_rn(v.z));
            uint32_t h3 = __half_as_ushort(__int2half_rn(v.w));
            uint2 p;
            p.x = h0 | (h1 << 16);
            p.y = h2 | (h3 << 16);
            dw[j] = p;
        }
    }
}

// ---------------- main GEMM: mma.sync f16 (f32 acc), mbarrier pipeline ----
// 256 threads = 8 warps. CTA tile 128(M) x 128(N); warp tile 32(M) x 64(N).
// Per-stage full/empty mbarriers replace __syncthreads: the produce-wait for
// chunk c+2 targets an empty[] signaled one chunk earlier, so warps drift up
// to a chunk instead of collapsing to the slowest warp at every boundary.
__global__ void __launch_bounds__(256, 2) qgemm_kernel(
    const float* __restrict__ scale,
    const float* __restrict__ bias,
    float* __restrict__ out
) {
    extern __shared__ char smem[];
    const uint32_t sbase = smem_u32(smem);
    const int tid = threadIdx.x;
    const int m0 = blockIdx.y * MT;
    const int n0 = blockIdx.x * NT;

    // mbarriers: full[s] at sbase + s*8, empty[s] at sbase + 24 + s*8
    const uint32_t mb_full  = sbase;
    const uint32_t mb_empty = sbase + 24;
    const uint32_t tiles    = sbase + 1024;

    if (tid == 0) {
        #pragma unroll
        for (int s = 0; s < STAGES; ++s) {
            MBARRIER_INIT(mb_full + s * 8, 256);    // cp.async noinc arrives
            MBARRIER_INIT(mb_empty + s * 8, 256);   // per-thread read-done arrives
        }
    }
    __syncthreads();

    const int lane = tid & 31;
    const int wid = tid >> 5;
    const int wm = wid & 3;      // 4 M-groups of 32 rows
    const int wn = wid >> 2;     // 2 N-groups of 64 cols

    // gmem byte-bases (row stride = KDIM * 2 bytes = 8192 = 1<<13)
    const char* pX = (const char*)g_X + ((size_t)m0 << 13);
    const char* pW = (const char*)g_W + ((size_t)n0 << 13);

    // ldmatrix address components (proven R6 pattern)
    const int rA = 32 * wm + (lane & 7) + ((lane >> 3) & 1) * 8;
    const int kaddA = ((lane >> 4) & 1) * 16;
    const uint32_t xmA = (uint32_t)((lane & 7) << 4);
    const int nrb = 64 * wn + (lane & 7) + ((lane >> 4) & 1) * 8;
    const int kaddB = ((lane >> 3) & 1) * 16;
    const uint32_t xmB = (uint32_t)((lane & 7) << 4);

    float acc[2][8][4];
    #pragma unroll
    for (int a = 0; a < 2; ++a)
        #pragma unroll
        for (int b = 0; b < 8; ++b)
            #pragma unroll
            for (int c = 0; c < 4; ++c) acc[a][b][c] = 0.0f;

    // ---- stage loader: A 16KB + B 16KB, 4 granules/thread each ----
    auto load_stage = [&](int stg, int c) {
        const uint32_t st = tiles + (uint32_t)stg * STAGE_BYTES;
        const uint32_t ko = (uint32_t)c << 7;       // c * 128 bytes along K
        #pragma unroll
        for (int i = 0; i < 4; ++i) {               // A + B: rows 0..127 each
            const int g = tid + i * 256;
            const int row = g >> 3;
            const int col = (g & 7) << 4;
            const uint32_t soff = (uint32_t)(row * 128) + ((uint32_t)col ^ (uint32_t)((row & 7) << 4));
            const size_t goff = ((size_t)row << 13) + ko + col;
            CP16(st + soff,          pX + goff);
            CP16(st + A_TILE + soff, pW + goff);
        }
    };

    // ---- prologue: chunks 0,1 into stages 0,1 (no wait needed) ----
    load_stage(0, 0); CP_ARRIVE(mb_full + 0 * 8);
    load_stage(1, 1); CP_ARRIVE(mb_full + 1 * 8);

    // ---- mainloop ----
    // consumer: chunk c uses stage s_cur = c%3, full-parity fp = (c/3)&1.
    // producer: at iteration c loads chunk c+2 into stage s_p=(c+2)%3 after
    // waiting empty[s_p] (signaled at end of chunk c-1); parity ep starts 1
    // (vacuous first wait on stage 2), flips when s_p wraps to 0.
    int s_cur = 0, fp = 0;
    int s_p = 2, ep = 1;
    for (int c = 0; c < NCHUNK; ++c) {
        MBARRIER_WAIT_PARITY(mb_full + s_cur * 8, fp);

        const uint32_t st = tiles + (uint32_t)s_cur * STAGE_BYTES;
        const uint32_t aA = st + (uint32_t)(rA * 128);
        const uint32_t aB = st + A_TILE + (uint32_t)(nrb * 128);

        // pull k-step 0 fragments before issuing the produce burst
        uint32_t af0[4], af1[4];
        uint32_t bf[4][4];
        {
            const uint32_t kA = ((uint32_t)kaddA) ^ xmA;
            const uint32_t kB = ((uint32_t)kaddB) ^ xmB;
            LDSM4(af0[0], af0[1], af0[2], af0[3], aA + kA);
            LDSM4(af1[0], af1[1], af1[2], af1[3], aA + (uint32_t)(16 * 128) + kA);
            #pragma unroll
            for (int p = 0; p < 4; ++p)
                LDSM4(bf[p][0], bf[p][1], bf[p][2], bf[p][3],
                      aB + (uint32_t)(p * 16 * 128) + kB);
        }

        if (c + 2 < NCHUNK) {
            MBARRIER_WAIT_PARITY(mb_empty + s_p * 8, ep);
            load_stage(s_p, c + 2);
            CP_ARRIVE(mb_full + s_p * 8);
        }

        #pragma unroll
        for (int ks = 0; ks < 4; ++ks) {
            if (ks > 0) {
                const uint32_t kA = ((uint32_t)(ks * 32 + kaddA)) ^ xmA;
                const uint32_t kB = ((uint32_t)(ks * 32 + kaddB)) ^ xmB;
                LDSM4(af0[0], af0[1], af0[2], af0[3], aA + kA);
                LDSM4(af1[0], af1[1], af1[2], af1[3], aA + (uint32_t)(16 * 128) + kA);
                #pragma unroll
                for (int p = 0; p < 4; ++p)
                    LDSM4(bf[p][0], bf[p][1], bf[p][2], bf[p][3],
                          aB + (uint32_t)(p * 16 * 128) + kB);
            }
            #pragma unroll
            for (int nt = 0; nt < 8; ++nt) {
                const uint32_t b0 = bf[nt >> 1][(nt & 1) * 2];
                const uint32_t b1 = bf[nt >> 1][(nt & 1) * 2 + 1];
                MMA_F16(acc[0][nt], af0[0], af0[1], af0[2], af0[3], b0, b1);
                MMA_F16(acc[1][nt], af1[0], af1[1], af1[2], af1[3], b0, b1);
            }
        }

        // this thread's reads of stage s_cur are complete (MMAs consumed regs)
        MBARRIER_ARRIVE(mb_empty + s_cur * 8);

        // rotate consumer stage; fp = (c/3)&1 flips when s_cur wraps to 0
        s_cur = (s_cur == 2) ? 0 : s_cur + 1;
        if (s_cur == 0) fp ^= 1;
        // rotate producer stage; ep flips when s_p wraps to 0
        s_p = (s_p == 2) ? 0 : s_p + 1;
        if (s_p == 0) ep ^= 1;
    }

    // ---- epilogue: y = scale[n] * acc + bias[n] ----
    const int ncol = n0 + 64 * wn + 2 * (lane & 3);
    const float* scn = scale + ncol;
    const float* bin = bias + ncol;
    #pragma unroll
    for (int mt = 0; mt < 2; ++mt) {
        const int mr0 = m0 + 32 * wm + 16 * mt + (lane >> 2);
        const int mr1 = mr0 + 8;
        float* o0 = out + (size_t)mr0 * NDIM + ncol;
        float* o1 = out + (size_t)mr1 * NDIM + ncol;
        #pragma unroll
        for (int nt = 0; nt < 8; ++nt) {
            const float2 ws = *(const float2*)(scn + 8 * nt);
            const float2 bb = *(const float2*)(bin + 8 * nt);
            float2 v0, v1;
            v0.x = ws.x * acc[mt][nt][0] + bb.x;
            v0.y = ws.y * acc[mt][nt][1] + bb.y;
            v1.x = ws.x * acc[mt][nt][2] + bb.x;
            v1.y = ws.y * acc[mt][nt][3] + bb.y;
            *(float2*)(o0 + 8 * nt) = v0;
            *(float2*)(o1 + 8 * nt) = v1;
        }
    }
}

// ---------------- launcher ----------------
extern "C" void kernel_launch(void* const* d_in, const int* in_sizes, int n_in,
                              void* d_out, int out_size) {
    const float* x     = (const float*)d_in[0];
    const int*   w     = (const int*)d_in[1];
    const float* scale = (const float*)d_in[2];
    const float* bias  = (const float*)d_in[3];
    float* out = (float*)d_out;

    cudaFuncSetAttribute(qgemm_kernel, cudaFuncAttributeMaxDynamicSharedMemorySize, SMEM_BYTES);

    cvt_kernel<<<4096, 256>>>(x, w);

    dim3 grid(NDIM / NT, MDIM / MT);   // (32, 64) = 2048 CTAs
    qgemm_kernel<<<grid, 256, SMEM_BYTES>>>(scale, bias, out);
}

// round 10
// speedup vs baseline: 1.2006x; 1.0976x over previous
#include <cuda_runtime.h>
#include <cuda_fp16.h>
#include <cstdint>
#include <cstddef>

// ---------------- problem sizes ----------------
#define MDIM 8192
#define NDIM 4096
#define KDIM 4096
#define MT 128          // CTA tile M
#define NT 128          // CTA tile N
#define KC 64           // K elements per chunk (fp16 -> 128B rows)
#define NCHUNK (KDIM / KC)          // 64
#define STAGES 3
#define A_TILE 16384                // 128 rows x 128B
#define B_TILE 16384                // 128 rows x 128B
#define STAGE_BYTES (A_TILE + B_TILE)       // 32768
#define SMEM_BYTES (STAGES * STAGE_BYTES)   // 98304 -> 2 CTAs/SM

// ---------------- device scratch (no allocation allowed) ----------------
__device__ __align__(128) __half g_X[(size_t)MDIM * KDIM];
__device__ __align__(128) __half g_W[(size_t)NDIM * KDIM];

// ---------------- PTX helpers (base sm_103 target only) -------------------
static __device__ __forceinline__ uint32_t smem_u32(const void* p) {
    uint32_t a;
    asm("{ .reg .u64 t; cvta.to.shared.u64 t, %1; cvt.u32.u64 %0, t; }" : "=r"(a) : "l"(p));
    return a;
}

#define CP16(dst, src) \
    asm volatile("cp.async.cg.shared.global [%0], [%1], 16;" :: "r"((uint32_t)(dst)), "l"(src) : "memory")
#define CP_COMMIT() asm volatile("cp.async.commit_group;" ::: "memory")
#define CP_WAIT(n)  asm volatile("cp.async.wait_group %0;" :: "n"(n) : "memory")

#define LDSM4(r0, r1, r2, r3, addr) \
    asm volatile("ldmatrix.sync.aligned.m8n8.x4.shared.b16 {%0,%1,%2,%3}, [%4];" \
                 : "=r"(r0), "=r"(r1), "=r"(r2), "=r"(r3) : "r"(addr))

// f16 MMA, fp32 accumulate: D[16x8] += A[16x16] * B[16x8]
#define MMA_F16(d, a0, a1, a2, a3, b0, b1) \
    asm volatile("mma.sync.aligned.m16n8k16.row.col.f32.f16.f16.f32 " \
                 "{%0,%1,%2,%3}, {%4,%5,%6,%7}, {%8,%9}, {%0,%1,%2,%3};" \
                 : "+f"((d)[0]), "+f"((d)[1]), "+f"((d)[2]), "+f"((d)[3]) \
                 : "r"(a0), "r"(a1), "r"(a2), "r"(a3), "r"(b0), "r"(b1))

// ---------------- fused prepass: x fp32->fp16, w int32->fp16 --------------
#define NX4 ((size_t)MDIM * KDIM / 4)
#define NW4 ((size_t)NDIM * KDIM / 4)
__global__ void __launch_bounds__(256) cvt_kernel(const float* __restrict__ x,
                                                  const int* __restrict__ w) {
    const float4* __restrict__ x4 = (const float4*)x;
    const int4* __restrict__ w4 = (const int4*)w;
    uint2* __restrict__ dx = (uint2*)g_X;
    uint2* __restrict__ dw = (uint2*)g_W;
    const size_t total = NX4 + NW4;
    size_t stride = (size_t)gridDim.x * blockDim.x;
    for (size_t i = (size_t)blockIdx.x * blockDim.x + threadIdx.x; i < total; i += stride) {
        if (i < NX4) {
            float4 v = x4[i];
            uint32_t h0 = __half_as_ushort(__float2half_rn(v.x));
            uint32_t h1 = __half_as_ushort(__float2half_rn(v.y));
            uint32_t h2 = __half_as_ushort(__float2half_rn(v.z));
            uint32_t h3 = __half_as_ushort(__float2half_rn(v.w));
            uint2 p;
            p.x = h0 | (h1 << 16);
            p.y = h2 | (h3 << 16);
            dx[i] = p;
        } else {
            const size_t j = i - NX4;
            int4 v = w4[j];
            uint32_t h0 = __half_as_ushort(__int2half_rn(v.x));
            uint32_t h1 = __half_as_ushort(__int2half_rn(v.y));
            uint32_t h2 = __half_as_ushort(__int2half_rn(v.z));
            uint32_t h3 = __half_as_ushort(__int2half_rn(v.w));
            uint2 p;
            p.x = h0 | (h1 << 16);
            p.y = h2 | (h3 << 16);
            dw[j] = p;
        }
    }
}

// ---------------- main GEMM: mma.sync f16 (f32 acc), cp.async 3-stage -----
// 128 threads = 4 warps. CTA tile 128(M) x 128(N); warp tile 64(M) x 64(N).
// 2 CTAs/SM. 4.0 MMA per LDSM.x4 (vs 2.67 at 32x64 warp tile) cuts L1/smem
// operand traffic 1.5x so the tensor pipe is fed with less datapath contention.
__global__ void __launch_bounds__(128, 2) qgemm_kernel(
    const float* __restrict__ scale,
    const float* __restrict__ bias,
    float* __restrict__ out
) {
    extern __shared__ char smem[];
    const uint32_t sbase = smem_u32(smem);
    const int tid = threadIdx.x;
    const int m0 = blockIdx.y * MT;
    const int n0 = blockIdx.x * NT;

    const int lane = tid & 31;
    const int wid = tid >> 5;
    const int wm = wid & 1;      // M half (64 rows)
    const int wn = wid >> 1;     // N half (64 cols)

    // gmem byte-bases (row stride = KDIM * 2 bytes = 8192 = 1<<13)
    const char* pX = (const char*)g_X + ((size_t)m0 << 13);
    const char* pW = (const char*)g_W + ((size_t)n0 << 13);

    // ldmatrix address components (proven pattern; base row within warp block)
    const int rA = 64 * wm + (lane & 7) + ((lane >> 3) & 1) * 8;
    const int kaddA = ((lane >> 4) & 1) * 16;
    const uint32_t xmA = (uint32_t)((lane & 7) << 4);
    const int nrb = 64 * wn + (lane & 7) + ((lane >> 4) & 1) * 8;
    const int kaddB = ((lane >> 3) & 1) * 16;
    const uint32_t xmB = (uint32_t)((lane & 7) << 4);

    float acc[4][8][4];
    #pragma unroll
    for (int a = 0; a < 4; ++a)
        #pragma unroll
        for (int b = 0; b < 8; ++b)
            #pragma unroll
            for (int c = 0; c < 4; ++c) acc[a][b][c] = 0.0f;

    // ---- stage loader: A 16KB + B 16KB, 8 granules/thread each ----
    auto load_stage = [&](int stg, int c) {
        const uint32_t st = sbase + (uint32_t)stg * STAGE_BYTES;
        const uint32_t ko = (uint32_t)c << 7;       // c * 128 bytes along K
        #pragma unroll
        for (int i = 0; i < 8; ++i) {               // A + B: rows 0..127 each
            const int g = tid + i * 128;
            const int row = g >> 3;
            const int col = (g & 7) << 4;
            const uint32_t soff = (uint32_t)(row * 128) + ((uint32_t)col ^ (uint32_t)((row & 7) << 4));
            const size_t goff = ((size_t)row << 13) + ko + col;
            CP16(st + soff,          pX + goff);
            CP16(st + A_TILE + soff, pW + goff);
        }
    };

    // ---- prologue: stages 0,1 ----
    load_stage(0, 0); CP_COMMIT();
    load_stage(1, 1); CP_COMMIT();

    // ---- mainloop ----
    int s_cur = 0;          // stage being computed
    int s_nxt = 2;          // stage to fill with chunk c+2
    for (int c = 0; c < NCHUNK; ++c) {
        CP_WAIT(1);
        __syncthreads();

        const uint32_t st = sbase + (uint32_t)s_cur * STAGE_BYTES;
        const uint32_t aA = st + (uint32_t)(rA * 128);
        const uint32_t aB = st + A_TILE + (uint32_t)(nrb * 128);

        // pull k-step 0 fragments ahead of the produce burst
        uint32_t af[4][4];
        uint32_t bf[4][4];
        {
            const uint32_t kA = ((uint32_t)kaddA) ^ xmA;
            const uint32_t kB = ((uint32_t)kaddB) ^ xmB;
            #pragma unroll
            for (int mb = 0; mb < 4; ++mb)
                LDSM4(af[mb][0], af[mb][1], af[mb][2], af[mb][3],
                      aA + (uint32_t)(mb * 16 * 128) + kA);
            #pragma unroll
            for (int p = 0; p < 4; ++p)
                LDSM4(bf[p][0], bf[p][1], bf[p][2], bf[p][3],
                      aB + (uint32_t)(p * 16 * 128) + kB);
        }

        if (c + 2 < NCHUNK) load_stage(s_nxt, c + 2);
        CP_COMMIT();

        #pragma unroll
        for (int ks = 0; ks < 4; ++ks) {
            if (ks > 0) {
                const uint32_t kA = ((uint32_t)(ks * 32 + kaddA)) ^ xmA;
                const uint32_t kB = ((uint32_t)(ks * 32 + kaddB)) ^ xmB;
                #pragma unroll
                for (int mb = 0; mb < 4; ++mb)
                    LDSM4(af[mb][0], af[mb][1], af[mb][2], af[mb][3],
                          aA + (uint32_t)(mb * 16 * 128) + kA);
                #pragma unroll
                for (int p = 0; p < 4; ++p)
                    LDSM4(bf[p][0], bf[p][1], bf[p][2], bf[p][3],
                          aB + (uint32_t)(p * 16 * 128) + kB);
            }
            #pragma unroll
            for (int mb = 0; mb < 4; ++mb) {
                #pragma unroll
                for (int nt = 0; nt < 8; ++nt) {
                    const uint32_t b0 = bf[nt >> 1][(nt & 1) * 2];
                    const uint32_t b1 = bf[nt >> 1][(nt & 1) * 2 + 1];
                    MMA_F16(acc[mb][nt], af[mb][0], af[mb][1], af[mb][2], af[mb][3], b0, b1);
                }
            }
        }
        // rotate stages
        s_cur = (s_cur == 2) ? 0 : s_cur + 1;
        s_nxt = (s_nxt == 2) ? 0 : s_nxt + 1;
    }

    // ---- epilogue: y = scale[n] * acc + bias[n] ----
    const int ncol = n0 + 64 * wn + 2 * (lane & 3);
    const float* scn = scale + ncol;
    const float* bin = bias + ncol;
    #pragma unroll
    for (int mb = 0; mb < 4; ++mb) {
        const int mr0 = m0 + 64 * wm + 16 * mb + (lane >> 2);
        const int mr1 = mr0 + 8;
        float* o0 = out + (size_t)mr0 * NDIM + ncol;
        float* o1 = out + (size_t)mr1 * NDIM + ncol;
        #pragma unroll
        for (int nt = 0; nt < 8; ++nt) {
            const float2 ws = *(const float2*)(scn + 8 * nt);
            const float2 bb = *(const float2*)(bin + 8 * nt);
            float2 v0, v1;
            v0.x = ws.x * acc[mb][nt][0] + bb.x;
            v0.y = ws.y * acc[mb][nt][1] + bb.y;
            v1.x = ws.x * acc[mb][nt][2] + bb.x;
            v1.y = ws.y * acc[mb][nt][3] + bb.y;
            *(float2*)(o0 + 8 * nt) = v0;
            *(float2*)(o1 + 8 * nt) = v1;
        }
    }
}

// ---------------- launcher ----------------
extern "C" void kernel_launch(void* const* d_in, const int* in_sizes, int n_in,
                              void* d_out, int out_size) {
    const float* x     = (const float*)d_in[0];
    const int*   w     = (const int*)d_in[1];
    const float* scale = (const float*)d_in[2];
    const float* bias  = (const float*)d_in[3];
    float* out = (float*)d_out;

    cudaFuncSetAttribute(qgemm_kernel, cudaFuncAttributeMaxDynamicSharedMemorySize, SMEM_BYTES);

    cvt_kernel<<<4096, 256>>>(x, w);

    dim3 grid(NDIM / NT, MDIM / MT);   // (32, 64) = 2048 CTAs
    qgemm_kernel<<<grid, 128, SMEM_BYTES>>>(scale, bias, out);
}